// round 13
// baseline (speedup 1.0000x reference)
#include <cuda_runtime.h>
#include <cuda_bf16.h>
#include <cstdint>

// Soft decision tree, DEPTH=8, 32 feats, 10 classes, B=131072.
// P(leaf) = (prod e over right edges) / (prod (1+e) over path), e = exp(x[f]-t).
// Fused kernel, 2 samples/thread (float2), 8-way subtree split (octant==warp):
// each thread replicates the top 3 levels then owns one depth-3 subtree
// (31 nodes). Combined rcp at depth-6; uint4-prepacked leaf class offsets.

#define DEPTH   8
#define N_FEAT  32
#define N_CLS   10
#define BT      256               // threads per block (8 warps = 8 octants)
#define SPB     64                // samples per block (32 pairs)
#define NPAIR   32
#define PADF    66                // padded floats per feature row
#define N_SUB   31                // nodes per depth-3 subtree

#define LOG2E 1.4426950408889634f

__device__ __forceinline__ float ex2f(float z) {
    float e; asm("ex2.approx.f32 %0, %1;" : "=f"(e) : "f"(z)); return e;
}
__device__ __forceinline__ float rcpf(float d) {
    float r; asm("rcp.approx.f32 %0, %1;" : "=f"(r) : "f"(d)); return r;
}
__device__ __forceinline__ float2 lds2(const char* p) { return *(const float2*)p; }

// ld = local depth in subtree (0..2 plain, 3 = depth-6 handler), j = local idx.
template <int ld, int j>
struct Walk {
    static __device__ __forceinline__ void run(float Na, float Da, float Nb, float Db,
                                               const char* xb, char* sb,
                                               const float2* ps, const uint4* pk) {
        float2 p  = ps[(1 << ld) - 1 + j];              // broadcast LDS.64
        float2 xv = lds2(xb + __float_as_int(p.y));     // pair LDS.64
        float ea = ex2f(fmaf(xv.x, LOG2E, p.x));
        float eb = ex2f(fmaf(xv.y, LOG2E, p.x));
        float Dna = fmaf(Da, ea, Da);                   // D*(1+e)
        float Dnb = fmaf(Db, eb, Db);
        Walk<ld + 1, 2 * j>::run(Na, Dna, Nb, Dnb, xb, sb, ps, pk);
        Walk<ld + 1, 2 * j + 1>::run(Na * ea, Dna, Nb * eb, Dnb, xb, sb, ps, pk);
    }
};

// Local depth 3 == tree depth 6: node + both depth-7 children; one rcp per
// sample serves both children: r = rcp(DL*DR); 1/DL = r*DR; 1/DR = r*DL.
template <int j>
struct Walk<3, j> {
    static __device__ __forceinline__ void run(float Na, float Da, float Nb, float Db,
                                               const char* xb, char* sb,
                                               const float2* ps, const uint4* pk) {
        float2 p  = ps[7 + j];
        float2 xv = lds2(xb + __float_as_int(p.y));
        float e6a = ex2f(fmaf(xv.x, LOG2E, p.x));
        float e6b = ex2f(fmaf(xv.y, LOG2E, p.x));
        float D6a = fmaf(Da, e6a, Da);
        float D6b = fmaf(Db, e6b, Db);
        float NRa = Na * e6a;
        float NRb = Nb * e6b;

        float2 pL  = ps[15 + 2 * j];
        float2 xL  = lds2(xb + __float_as_int(pL.y));
        float eLa = ex2f(fmaf(xL.x, LOG2E, pL.x));
        float eLb = ex2f(fmaf(xL.y, LOG2E, pL.x));
        float DLa = fmaf(D6a, eLa, D6a);
        float DLb = fmaf(D6b, eLb, D6b);

        float2 pR  = ps[16 + 2 * j];
        float2 xR  = lds2(xb + __float_as_int(pR.y));
        float eRa = ex2f(fmaf(xR.x, LOG2E, pR.x));
        float eRb = ex2f(fmaf(xR.y, LOG2E, pR.x));
        float DRa = fmaf(D6a, eRa, D6a);
        float DRb = fmaf(D6b, eRb, D6b);

        float ra  = rcpf(DLa * DRa);
        float rb  = rcpf(DLb * DRb);
        float iLa = ra * DRa, iRa = ra * DLa;
        float iLb = rb * DRb, iRb = rb * DLb;

        float PLLa = Na * iLa,   PLLb = Nb * iLb;
        float PLRa = PLLa * eLa, PLRb = PLLb * eLb;
        float PRLa = NRa * iRa,  PRLb = NRb * iRb;
        float PRRa = PRLa * eRa, PRRb = PRLb * eRb;

        uint4 k = pk[j];                                // broadcast LDS.128
        {
            float2* a = (float2*)(sb + k.x);
            float2 v = *a; v.x += PLLa; v.y += PLLb; *a = v;
        }
        {
            float2* a = (float2*)(sb + k.y);
            float2 v = *a; v.x += PLRa; v.y += PLRb; *a = v;
        }
        {
            float2* a = (float2*)(sb + k.z);
            float2 v = *a; v.x += PRLa; v.y += PRLb; *a = v;
        }
        {
            float2* a = (float2*)(sb + k.w);
            float2 v = *a; v.x += PRRa; v.y += PRRb; *a = v;
        }
    }
};

__global__ void __launch_bounds__(BT, 5)
dt_kernel(const float* __restrict__ x,
          const float* __restrict__ thr,
          const int*   __restrict__ feats,
          const int*   __restrict__ cls,
          float* __restrict__ out) {
    __shared__ __align__(16) float    xs[N_FEAT * PADF];      // 8.25 KB
    __shared__ __align__(16) float    sacc[8 * N_CLS * SPB];  // 20 KB
    __shared__ __align__(8)  float2   s_top[7];               // depths 0..2
    __shared__ __align__(8)  float2   s_ps[8 * N_SUB];        // 2.0 KB
    __shared__ __align__(16) uint4    s_pk[64];               // 1.0 KB: [oct][j]

    const int tid = threadIdx.x;
    const int bs  = blockIdx.x * SPB;
    const int oct = tid >> 5;              // octant == warp index
    const int pr  = tid & (NPAIR - 1);     // sample-pair index (lane)

    // ---- per-block param prep ----
    if (tid < 7) {
        s_top[tid] = make_float2(-thr[tid] * LOG2E, __int_as_float(feats[tid] * PADF * 4));
    }
    if (tid < 8 * N_SUB) {                 // 248 entries
        int oo  = tid / N_SUB;
        int rem = tid - oo * N_SUB;        // 0..30, level order within subtree
        int ldp = 31 - __clz(rem + 1);     // 0..4
        int j   = rem + 1 - (1 << ldp);
        int g   = ((1 << (ldp + 3)) - 1) + oo * (1 << ldp) + j;
        s_ps[tid] = make_float2(-thr[g] * LOG2E, __int_as_float(feats[g] * PADF * 4));
    }
    if (tid < 64) {                        // global d6 index = tid; 4 leaves each
        int lb = tid * 4;
        s_pk[tid] = make_uint4((uint32_t)cls[lb + 0] * (SPB * 4),
                               (uint32_t)cls[lb + 1] * (SPB * 4),
                               (uint32_t)cls[lb + 2] * (SPB * 4),
                               (uint32_t)cls[lb + 3] * (SPB * 4));
    }

    // ---- stage 64 samples x 32 feats, coalesced LDG.128 ----
#pragma unroll
    for (int k = 0; k < (SPB * N_FEAT / 4) / BT; k++) {
        int idx = tid + k * BT;
        int s   = idx >> 3;
        int c4  = idx & 7;
        float4 v = reinterpret_cast<const float4*>(x + (size_t)(bs + s) * N_FEAT)[c4];
        xs[(c4 * 4 + 0) * PADF + s] = v.x;
        xs[(c4 * 4 + 1) * PADF + s] = v.y;
        xs[(c4 * 4 + 2) * PADF + s] = v.z;
        xs[(c4 * 4 + 3) * PADF + s] = v.w;
    }

    char* sb = (char*)sacc + oct * (N_CLS * SPB * 4) + 8 * pr;
#pragma unroll
    for (int c = 0; c < N_CLS; c++)
        *(float2*)(sb + c * (SPB * 4)) = make_float2(0.f, 0.f);

    __syncthreads();

    const char* xb = (const char*)xs + 8 * pr;
    const float2* ps = s_ps + oct * N_SUB;
    const uint4*  pk = s_pk + oct * 8;

    // replicated top 3 levels (root, depth-1, depth-2 ancestors of this octant)
    float2 p0  = s_top[0];
    float2 xv0 = lds2(xb + __float_as_int(p0.y));
    float e0a = ex2f(fmaf(xv0.x, LOG2E, p0.x));
    float e0b = ex2f(fmaf(xv0.y, LOG2E, p0.x));
    float Da = e0a + 1.f;
    float Db = e0b + 1.f;
    float Na = (oct & 4) ? e0a : 1.0f;
    float Nb = (oct & 4) ? e0b : 1.0f;

    float2 p1  = s_top[1 + (oct >> 2)];
    float2 xv1 = lds2(xb + __float_as_int(p1.y));
    float e1a = ex2f(fmaf(xv1.x, LOG2E, p1.x));
    float e1b = ex2f(fmaf(xv1.y, LOG2E, p1.x));
    Da = fmaf(Da, e1a, Da);
    Db = fmaf(Db, e1b, Db);
    if (oct & 2) { Na *= e1a; Nb *= e1b; }

    float2 p2  = s_top[3 + (oct >> 1)];
    float2 xv2 = lds2(xb + __float_as_int(p2.y));
    float e2a = ex2f(fmaf(xv2.x, LOG2E, p2.x));
    float e2b = ex2f(fmaf(xv2.y, LOG2E, p2.x));
    Da = fmaf(Da, e2a, Da);
    Db = fmaf(Db, e2b, Db);
    if (oct & 1) { Na *= e2a; Nb *= e2b; }

    Walk<0, 0>::run(Na, Da, Nb, Db, xb, sb, ps, pk);

    __syncthreads();

    // combine 8 octant-accumulators, write out (threads 0..63, one sample each)
    if (tid < SPB) {
        float a[N_CLS];
#pragma unroll
        for (int c = 0; c < N_CLS; c++) {
            float v = 0.f;
#pragma unroll
            for (int oo = 0; oo < 8; oo++)
                v += sacc[oo * (N_CLS * SPB) + c * SPB + tid];
            a[c] = v;
        }
        float* o = out + (size_t)(bs + tid) * N_CLS;
#pragma unroll
        for (int c = 0; c < N_CLS; c += 2)
            *(float2*)(o + c) = make_float2(a[c], a[c + 1]);
    }
}

extern "C" void kernel_launch(void* const* d_in, const int* in_sizes, int n_in,
                              void* d_out, int out_size) {
    const float* x     = (const float*)d_in[0];
    const float* thr   = (const float*)d_in[1];
    const int*   feats = (const int*)d_in[2];
    const int*   cls   = (const int*)d_in[3];
    float*       out   = (float*)d_out;

    const int B = in_sizes[0] / N_FEAT;

    dt_kernel<<<B / SPB, BT>>>(x, thr, feats, cls, out);
}

// round 14
// speedup vs baseline: 1.0880x; 1.0880x over previous
#include <cuda_runtime.h>
#include <cuda_bf16.h>
#include <cstdint>

// Soft decision tree, DEPTH=8, 32 feats, 10 classes, B=131072.
// P(leaf) = (prod e over right edges) / (prod (1+e) over path), e = exp(x[f]-t).
// R10 skeleton: fused kernel, 2 samples/thread (float2), 4-way subtree split
// (quarter==warp-of-4? quarter==tid>>5 pairs of warps... quarter==warp group),
// combined rcp at depth-6. This round: packed d6 records (2x LDS.128 for
// p6/pL/pR params) + uint4-prepacked leaf class offsets (1x LDS.128, no LOPs).

#define DEPTH   8
#define N_FEAT  32
#define N_CLS   10
#define BT      128               // threads per block
#define SPB     64                // samples per block (32 pairs x 4 quarter-warps)
#define NPAIR   32
#define PADF    66                // padded floats per feature row
#define N_INNER 15                // inner nodes per quarter subtree (depths 2..5)

#define LOG2E 1.4426950408889634f

__device__ __forceinline__ float ex2f(float z) {
    float e; asm("ex2.approx.f32 %0, %1;" : "=f"(e) : "f"(z)); return e;
}
__device__ __forceinline__ float rcpf(float d) {
    float r; asm("rcp.approx.f32 %0, %1;" : "=f"(r) : "f"(d)); return r;
}
__device__ __forceinline__ float2 lds2(const char* p) { return *(const float2*)p; }

// ld = local depth (0..3 plain, 4 = depth-6 handler), j = local node index.
template <int ld, int j>
struct Walk {
    static __device__ __forceinline__ void run(float Na, float Da, float Nb, float Db,
                                               const char* xb, char* sb,
                                               const float2* ps, const float4* d6r,
                                               const uint4* pk) {
        float2 p  = ps[(1 << ld) - 1 + j];              // broadcast LDS.64
        float2 xv = lds2(xb + __float_as_int(p.y));     // pair LDS.64
        float ea = ex2f(fmaf(xv.x, LOG2E, p.x));
        float eb = ex2f(fmaf(xv.y, LOG2E, p.x));
        float Dna = fmaf(Da, ea, Da);                   // D*(1+e)
        float Dnb = fmaf(Db, eb, Db);
        Walk<ld + 1, 2 * j>::run(Na, Dna, Nb, Dnb, xb, sb, ps, d6r, pk);
        Walk<ld + 1, 2 * j + 1>::run(Na * ea, Dna, Nb * eb, Dnb, xb, sb, ps, d6r, pk);
    }
};

// Depth-6 handler: node + both depth-7 children; one rcp per sample serves
// both children: r = rcp(DL*DR); 1/DL = r*DR; 1/DR = r*DL.
// Params come as two packed float4 records: r0={p6x,off6,pLx,offL},
// r1={pRx,offR,-,-}; leaf class byte-offsets as one uint4.
template <int j>
struct Walk<4, j> {
    static __device__ __forceinline__ void run(float Na, float Da, float Nb, float Db,
                                               const char* xb, char* sb,
                                               const float2* ps, const float4* d6r,
                                               const uint4* pk) {
        float4 r0 = d6r[2 * j];                         // broadcast LDS.128
        float4 r1 = d6r[2 * j + 1];                     // broadcast LDS.128

        float2 x6 = lds2(xb + __float_as_int(r0.y));
        float e6a = ex2f(fmaf(x6.x, LOG2E, r0.x));
        float e6b = ex2f(fmaf(x6.y, LOG2E, r0.x));
        float D6a = fmaf(Da, e6a, Da);
        float D6b = fmaf(Db, e6b, Db);
        float NRa = Na * e6a;
        float NRb = Nb * e6b;

        float2 xL = lds2(xb + __float_as_int(r0.w));
        float eLa = ex2f(fmaf(xL.x, LOG2E, r0.z));
        float eLb = ex2f(fmaf(xL.y, LOG2E, r0.z));
        float DLa = fmaf(D6a, eLa, D6a);
        float DLb = fmaf(D6b, eLb, D6b);

        float2 xR = lds2(xb + __float_as_int(r1.y));
        float eRa = ex2f(fmaf(xR.x, LOG2E, r1.x));
        float eRb = ex2f(fmaf(xR.y, LOG2E, r1.x));
        float DRa = fmaf(D6a, eRa, D6a);
        float DRb = fmaf(D6b, eRb, D6b);

        float ra  = rcpf(DLa * DRa);
        float rb  = rcpf(DLb * DRb);
        float iLa = ra * DRa, iRa = ra * DLa;
        float iLb = rb * DRb, iRb = rb * DLb;

        float PLLa = Na * iLa,   PLLb = Nb * iLb;       // leaf 4j   (L of pL)
        float PLRa = PLLa * eLa, PLRb = PLLb * eLb;     // leaf 4j+1 (R of pL)
        float PRLa = NRa * iRa,  PRLb = NRb * iRb;      // leaf 4j+2 (L of pR)
        float PRRa = PRLa * eRa, PRRb = PRLb * eRb;     // leaf 4j+3 (R of pR)

        uint4 k = pk[j];                                // broadcast LDS.128
        {
            float2* a = (float2*)(sb + k.x);
            float2 v = *a; v.x += PLLa; v.y += PLLb; *a = v;
        }
        {
            float2* a = (float2*)(sb + k.y);
            float2 v = *a; v.x += PLRa; v.y += PLRb; *a = v;
        }
        {
            float2* a = (float2*)(sb + k.z);
            float2 v = *a; v.x += PRLa; v.y += PRLb; *a = v;
        }
        {
            float2* a = (float2*)(sb + k.w);
            float2 v = *a; v.x += PRRa; v.y += PRRb; *a = v;
        }
    }
};

__global__ void __launch_bounds__(BT, 10)
dt_kernel(const float* __restrict__ x,
          const float* __restrict__ thr,
          const int*   __restrict__ feats,
          const int*   __restrict__ cls,
          float* __restrict__ out) {
    __shared__ __align__(16) float    xs[N_FEAT * PADF];      // 8.25 KB
    __shared__ __align__(16) float    sacc[4 * N_CLS * SPB];  // 10 KB
    __shared__ __align__(8)  float2   s_top[3];
    __shared__ __align__(8)  float2   s_ps[4 * N_INNER];      // 480 B (depths 2..5)
    __shared__ __align__(16) float4   s_d6[64 * 2];           // 2 KB  (d6+d7 params)
    __shared__ __align__(16) uint4    s_pk[64];               // 1 KB  leaf offsets

    const int tid = threadIdx.x;
    const int bs  = blockIdx.x * SPB;
    const int q   = tid >> 5;              // quarter == warp index
    const int pr  = tid & (NPAIR - 1);     // sample-pair index (lane)

    // ---- per-block param prep ----
    if (tid < 3) {
        s_top[tid] = make_float2(-thr[tid] * LOG2E, __int_as_float(feats[tid] * PADF * 4));
    }
    if (tid < 4 * N_INNER) {               // 60 inner params (tree depths 2..5)
        int qq  = tid / N_INNER;
        int rem = tid - qq * N_INNER;      // 0..14, level order
        int ldp = 31 - __clz(rem + 1);     // 0..3
        int j   = rem + 1 - (1 << ldp);
        int g   = ((1 << (ldp + 2)) - 1) + qq * (1 << ldp) + j;
        s_ps[tid] = make_float2(-thr[g] * LOG2E, __int_as_float(feats[g] * PADF * 4));
    }
    {                                      // 128 float4 d6 records
        int d6 = tid >> 1;                 // global in-level d6 index 0..63
        int w  = tid & 1;
        if (w == 0) {
            int g6 = 63 + d6;              // depth-6 node
            int gL = 127 + 2 * d6;         // left d7 child
            s_d6[tid] = make_float4(-thr[g6] * LOG2E,
                                    __int_as_float(feats[g6] * PADF * 4),
                                    -thr[gL] * LOG2E,
                                    __int_as_float(feats[gL] * PADF * 4));
        } else {
            int gR = 128 + 2 * d6;         // right d7 child
            s_d6[tid] = make_float4(-thr[gR] * LOG2E,
                                    __int_as_float(feats[gR] * PADF * 4),
                                    0.f, 0.f);
        }
    }
    if (tid < 64) {                        // leaf class byte-offsets per d6
        int lb = tid * 4;
        s_pk[tid] = make_uint4((uint32_t)cls[lb + 0] * (SPB * 4),
                               (uint32_t)cls[lb + 1] * (SPB * 4),
                               (uint32_t)cls[lb + 2] * (SPB * 4),
                               (uint32_t)cls[lb + 3] * (SPB * 4));
    }

    // ---- stage 64 samples x 32 feats, coalesced LDG.128 ----
#pragma unroll
    for (int k = 0; k < (SPB * N_FEAT / 4) / BT; k++) {
        int idx = tid + k * BT;
        int s   = idx >> 3;
        int c4  = idx & 7;
        float4 v = reinterpret_cast<const float4*>(x + (size_t)(bs + s) * N_FEAT)[c4];
        xs[(c4 * 4 + 0) * PADF + s] = v.x;
        xs[(c4 * 4 + 1) * PADF + s] = v.y;
        xs[(c4 * 4 + 2) * PADF + s] = v.z;
        xs[(c4 * 4 + 3) * PADF + s] = v.w;
    }

    char* sb = (char*)sacc + q * (N_CLS * SPB * 4) + 8 * pr;
#pragma unroll
    for (int c = 0; c < N_CLS; c++)
        *(float2*)(sb + c * (SPB * 4)) = make_float2(0.f, 0.f);

    __syncthreads();

    const char* xb = (const char*)xs + 8 * pr;
    const float2* ps  = s_ps + q * N_INNER;
    const float4* d6r = s_d6 + q * 32;     // 16 d6 records x2 per quarter
    const uint4*  pk  = s_pk + q * 16;

    // replicated top 2 levels
    float2 p0  = s_top[0];
    float2 xv0 = lds2(xb + __float_as_int(p0.y));
    float e0a = ex2f(fmaf(xv0.x, LOG2E, p0.x));
    float e0b = ex2f(fmaf(xv0.y, LOG2E, p0.x));
    float Da = e0a + 1.f;
    float Db = e0b + 1.f;
    float Na = (q & 2) ? e0a : 1.0f;
    float Nb = (q & 2) ? e0b : 1.0f;

    float2 p1  = s_top[1 + (q >> 1)];
    float2 xv1 = lds2(xb + __float_as_int(p1.y));
    float e1a = ex2f(fmaf(xv1.x, LOG2E, p1.x));
    float e1b = ex2f(fmaf(xv1.y, LOG2E, p1.x));
    Da = fmaf(Da, e1a, Da);
    Db = fmaf(Db, e1b, Db);
    if (q & 1) { Na *= e1a; Nb *= e1b; }

    Walk<0, 0>::run(Na, Da, Nb, Db, xb, sb, ps, d6r, pk);

    __syncthreads();

    // combine 4 quarter-accumulators, write out (threads 0..63, one sample each)
    if (tid < SPB) {
        float a[N_CLS];
#pragma unroll
        for (int c = 0; c < N_CLS; c++) {
            float v = 0.f;
#pragma unroll
            for (int qq = 0; qq < 4; qq++)
                v += sacc[qq * (N_CLS * SPB) + c * SPB + tid];
            a[c] = v;
        }
        float* o = out + (size_t)(bs + tid) * N_CLS;
#pragma unroll
        for (int c = 0; c < N_CLS; c += 2)
            *(float2*)(o + c) = make_float2(a[c], a[c + 1]);
    }
}

extern "C" void kernel_launch(void* const* d_in, const int* in_sizes, int n_in,
                              void* d_out, int out_size) {
    const float* x     = (const float*)d_in[0];
    const float* thr   = (const float*)d_in[1];
    const int*   feats = (const int*)d_in[2];
    const int*   cls   = (const int*)d_in[3];
    float*       out   = (float*)d_out;

    const int B = in_sizes[0] / N_FEAT;

    dt_kernel<<<B / SPB, BT>>>(x, thr, feats, cls, out);
}